// round 11
// baseline (speedup 1.0000x reference)
#include <cuda_runtime.h>
#include <math.h>

#define B   8
#define NPT 2048
#define KNN 10
#define EPS 1e-5f

// ---------------- scratch (device globals; referenced from DEVICE code only)
__device__ float    g_cat  [B * 192 * NPT];
__device__ unsigned g_cat_h[B * 192 * NPT];
__device__ unsigned g_cat_l[B * 192 * NPT];
__device__ float    g_x1pm [B * NPT * 64];   // point-major x1 (for edge2 gather)
__device__ float    g_x2pm [B * NPT * 64];   // point-major x2 (for edge3 gather)
__device__ float    g_sq [B * NPT];
__device__ int      g_idx[B * NPT * KNN];
__device__ int      g_glob_i[B * 1024];
__device__ float    g_bias7[B * 512];
__device__ unsigned g_h7h[B * 512 * NPT];
__device__ unsigned g_h7l[B * 512 * NPT];
__device__ float    g_h8 [B * 256 * NPT];
__device__ unsigned g_wh[425984];
__device__ unsigned g_wl[425984];

// fast mish: tanh(softplus(x)) = u/(u+2), u = t(t+2), t = e^x
__device__ __forceinline__ float mishf(float x) {
    float t = expf(x);
    float u = t * (t + 2.f);
    float r = x * u / (u + 2.f);
    return (x > 20.f) ? x : r;
}
__device__ __forceinline__ unsigned f2tf32(float x) {
    unsigned r; asm("cvt.rna.tf32.f32 %0, %1;" : "=r"(r) : "f"(x)); return r;
}
__device__ __forceinline__ int f2ord(float f) {
    int i = __float_as_int(f); return (i >= 0) ? i : (i ^ 0x7fffffff);
}
__device__ __forceinline__ float ord2f(int o) {
    return __int_as_float((o >= 0) ? o : (o ^ 0x7fffffff));
}
__device__ __forceinline__ unsigned long long pack2(float x, float y) {
    unsigned long long r;
    asm("mov.b64 %0, {%1, %2};" : "=l"(r) : "f"(x), "f"(y));
    return r;
}
__device__ __forceinline__ void unpack2(unsigned long long v, float& lo, float& hi) {
    asm("mov.b64 {%0, %1}, %2;" : "=f"(lo), "=f"(hi) : "l"(v));
}
__device__ __forceinline__ void ffma2(unsigned long long& acc,
                                      unsigned long long a, unsigned long long b) {
    asm("fma.rn.f32x2 %0, %1, %2, %0;" : "+l"(acc) : "l"(a), "l"(b));
}

// ---------------- weight pre-conversion to tf32 hi/lo ----------------------
__global__ void convw_kernel(const float* __restrict__ w, int srcLd, int srcOff,
                             int dstOff, int M, int Kd) {
    int i = blockIdx.x * blockDim.x + threadIdx.x;
    if (i >= M * Kd) return;
    int m = i / Kd, k = i % Kd;
    float x = w[(size_t)m * srcLd + srcOff + k];
    unsigned h = f2tf32(x);
    g_wh[dstOff + i] = h;
    g_wl[dstOff + i] = f2tf32(x - __uint_as_float(h));
}

// ---------------- squared norms --------------------------------------------
template<int C>
__global__ void sq_kernel(const float* __restrict__ Xext, int chanOff) {
    int p = blockIdx.x * blockDim.x + threadIdx.x;
    if (p >= B * NPT) return;
    int b = p / NPT, n = p % NPT;
    const float* xp = (C == 3) ? (Xext + b * 3 * NPT + n)
                               : (g_cat + b * 192 * NPT + chanOff * NPT + n);
    float s = 0.f;
#pragma unroll
    for (int c = 0; c < C; c++) { float v = xp[c * NPT]; s = fmaf(v, v, s); }
    g_sq[p] = s;
}

// ---------------- kNN: packed-f32x2 distances + warp-local top-10 ----------
template<int C, int IT>
__global__ void knn_kernel(const float* __restrict__ Xext, int chanOff) {
    extern __shared__ unsigned long long sm64[];
    unsigned long long* s_xi2 = sm64;                  // IT*C (query dup-packed)
    float* s_neg = (float*)(sm64 + IT * C);            // IT*NPT

    int b = blockIdx.y, i0 = blockIdx.x * IT, tid = threadIdx.x;
    int lane = tid & 31, w = tid >> 5;
    const float* Xb = (C == 3) ? (Xext + b * 3 * NPT)
                               : (g_cat + b * 192 * NPT + chanOff * NPT);
    for (int l = tid; l < IT * C; l += 256) {
        int ii = l / C, c = l % C;
        float v = Xb[c * NPT + i0 + ii];
        s_xi2[ii * C + c] = pack2(v, v);
    }
    __syncthreads();
    float sqi[IT];
#pragma unroll
    for (int ii = 0; ii < IT; ii++) sqi[ii] = g_sq[b * NPT + i0 + ii];

    // distance: thread handles 2 consecutive keys per block-iter (f32x2 fma)
#pragma unroll
    for (int jb = 0; jb < NPT / 512; jb++) {
        int j0 = jb * 512 + tid * 2;
        unsigned long long acc2[IT];
#pragma unroll
        for (int ii = 0; ii < IT; ii++) acc2[ii] = 0ull;
        for (int c = 0; c < C; c++) {
            unsigned long long kv = *(const unsigned long long*)&Xb[c * NPT + j0];
#pragma unroll
            for (int ii = 0; ii < IT; ii++) {
                unsigned long long q = s_xi2[ii * C + c];
                ffma2(acc2[ii], kv, q);
            }
        }
        float2 sqj = *(const float2*)&g_sq[b * NPT + j0];
#pragma unroll
        for (int ii = 0; ii < IT; ii++) {
            float a0, a1; unpack2(acc2[ii], a0, a1);
            float2 o;
            o.x = 2.f * a0 - sqi[ii] - sqj.x;
            o.y = 2.f * a1 - sqi[ii] - sqj.y;
            *(float2*)&s_neg[ii * NPT + j0] = o;
        }
    }
    __syncthreads();

    // --- warp-local top-K for point w (lane owns stripe j%32==lane) ---
    float* neg = s_neg + w * NPT;
    float v = -INFINITY; int id = NPT;
#pragma unroll 8
    for (int i = 0; i < NPT / 32; i++) {
        int j = lane + 32 * i;
        float nv = neg[j];
        if (nv > v) { v = nv; id = j; }       // ascending j: ties keep lowest idx
    }
    int* op = &g_idx[(b * NPT + i0 + w) * KNN];
    for (int r = 0; r < KNN; r++) {
        float bv = v; int bi = id;
#pragma unroll
        for (int s = 16; s > 0; s >>= 1) {
            float ov = __shfl_xor_sync(0xffffffffu, bv, s);
            int   oi = __shfl_xor_sync(0xffffffffu, bi, s);
            if (ov > bv || (ov == bv && oi < bi)) { bv = ov; bi = oi; }
        }
        if (lane == 0) op[r] = bi;
        if ((bi & 31) == lane) {
            neg[bi] = -INFINITY;
            v = -INFINITY; id = NPT;
            for (int i = 0; i < NPT / 32; i++) {
                int j = lane + 32 * i;
                float nv = neg[j];
                if (nv > v) { v = nv; id = j; }
            }
        }
    }
}

// ---------------- cat writer (float + tf32 hi/lo mirrors) ------------------
__device__ __forceinline__ void cat_store(int b, int ch, int i, float v) {
    size_t o = (size_t)b * 192 * NPT + (size_t)ch * NPT + i;
    g_cat[o] = v;
    unsigned h = f2tf32(v);
    g_cat_h[o] = h;
    g_cat_l[o] = f2tf32(v - __uint_as_float(h));
}

// ---------------- edge conv stage 1 (6 -> 64 -> 64, max over K) -----------
__global__ void edge1_kernel(const float* __restrict__ X,
                             const float* __restrict__ w1, const float* __restrict__ w2,
                             const float* __restrict__ g15, const float* __restrict__ b15,
                             const float* __restrict__ m15, const float* __restrict__ v15)
{
    __shared__ float w1T[6 * 64];
    __shared__ float w2T[64 * 64];
    __shared__ float ctr[4][4];
    __shared__ float nb[4][KNN][4];
    __shared__ float h1s[4][KNN][64];
    int tid = threadIdx.x;
    int g = tid >> 6, t = tid & 63;
    int b = blockIdx.y;
    int i = blockIdx.x * 4 + g;
    for (int l = tid; l < 384; l += 256) { int o = l / 6, c = l % 6; w1T[c * 64 + o] = w1[l]; }
    for (int l = tid; l < 4096; l += 256) { int o = l >> 6, c = l & 63; w2T[c * 64 + o] = w2[l]; }
    const int* idxp = &g_idx[(b * NPT + i) * KNN];
    if (t < 3) ctr[g][t] = X[b * 3 * NPT + t * NPT + i];
    if (t < 30) {
        int k = t / 3, c = t % 3;
        nb[g][k][c] = X[b * 3 * NPT + c * NPT + idxp[k]];
    }
    float s1 = g15[t] * rsqrtf(v15[t] + EPS);
    float t1 = b15[t] - m15[t] * s1;
    float s2 = g15[64 + t] * rsqrtf(v15[64 + t] + EPS);
    float t2 = b15[64 + t] - m15[64 + t] * s2;
    __syncthreads();

    float base = 0.f;
#pragma unroll
    for (int c = 0; c < 3; c++)
        base += (w1T[(3 + c) * 64 + t] - w1T[c * 64 + t]) * ctr[g][c];
#pragma unroll
    for (int k = 0; k < KNN; k++) {
        float h = base;
#pragma unroll
        for (int c = 0; c < 3; c++) h = fmaf(w1T[c * 64 + t], nb[g][k][c], h);
        h1s[g][k][t] = mishf(fmaf(h, s1, t1));
    }
    __syncthreads();

    float h2[KNN];
#pragma unroll
    for (int k = 0; k < KNN; k++) h2[k] = 0.f;
#pragma unroll
    for (int cb = 0; cb < 4; cb++) {
        float wr[16];
#pragma unroll
        for (int c = 0; c < 16; c++) wr[c] = w2T[(cb * 16 + c) * 64 + t];
#pragma unroll
        for (int k = 0; k < KNN; k++) {
            const float4* hp = (const float4*)&h1s[g][k][cb * 16];
#pragma unroll
            for (int q = 0; q < 4; q++) {
                float4 hv = hp[q];
                h2[k] = fmaf(wr[q * 4 + 0], hv.x, h2[k]);
                h2[k] = fmaf(wr[q * 4 + 1], hv.y, h2[k]);
                h2[k] = fmaf(wr[q * 4 + 2], hv.z, h2[k]);
                h2[k] = fmaf(wr[q * 4 + 3], hv.w, h2[k]);
            }
        }
    }
    float mx = -INFINITY;
#pragma unroll
    for (int k = 0; k < KNN; k++) mx = fmaxf(mx, mishf(fmaf(h2[k], s2, t2)));
    cat_store(b, t, i, mx);
    g_x1pm[((size_t)b * NPT + i) * 64 + t] = mx;
}

// ---------------- edge conv stage 2 (128 -> 64 -> 64, max over K) ---------
extern __shared__ float dsm2[];
__global__ void edge2_kernel(const float* __restrict__ w3, const float* __restrict__ w4,
                             const float* __restrict__ g15, const float* __restrict__ b15,
                             const float* __restrict__ m15, const float* __restrict__ v15)
{
    float* w3T = dsm2;                        // 8192
    float* w4T = dsm2 + 8192;                 // 4096
    float* ctr = dsm2 + 12288;                // 4*64
    float* nb  = dsm2 + 12544;                // 4*10*64
    float* h1s = dsm2 + 15104;                // 4*10*64
    int tid = threadIdx.x;
    int g = tid >> 6, t = tid & 63;
    int b = blockIdx.y;
    int i = blockIdx.x * 4 + g;
    for (int l = tid; l < 8192; l += 256) { int o = l >> 7, c = l & 127; w3T[c * 64 + o] = w3[l]; }
    for (int l = tid; l < 4096; l += 256) { int o = l >> 6, c = l & 63;  w4T[c * 64 + o] = w4[l]; }
    const int* idxp = &g_idx[(b * NPT + i) * KNN];
    ctr[g * 64 + t] = g_x1pm[((size_t)b * NPT + i) * 64 + t];    // coalesced
    int jn[KNN];
#pragma unroll
    for (int k = 0; k < KNN; k++) jn[k] = idxp[k];
#pragma unroll
    for (int k = 0; k < KNN; k++)
        nb[(g * KNN + k) * 64 + t] = g_x1pm[((size_t)b * NPT + jn[k]) * 64 + t];  // coalesced
    float s1 = g15[128 + t] * rsqrtf(v15[128 + t] + EPS);
    float t1 = b15[128 + t] - m15[128 + t] * s1;
    float s2 = g15[192 + t] * rsqrtf(v15[192 + t] + EPS);
    float t2 = b15[192 + t] - m15[192 + t] * s2;
    __syncthreads();

    float base = 0.f;
    for (int c = 0; c < 64; c++)
        base += (w3T[(64 + c) * 64 + t] - w3T[c * 64 + t]) * ctr[g * 64 + c];
    float h1[KNN];
#pragma unroll
    for (int k = 0; k < KNN; k++) h1[k] = base;
#pragma unroll
    for (int cb = 0; cb < 4; cb++) {
        float wr[16];
#pragma unroll
        for (int c = 0; c < 16; c++) wr[c] = w3T[(cb * 16 + c) * 64 + t];
#pragma unroll
        for (int k = 0; k < KNN; k++) {
            const float4* np = (const float4*)&nb[(g * KNN + k) * 64 + cb * 16];
#pragma unroll
            for (int q = 0; q < 4; q++) {
                float4 nv = np[q];
                h1[k] = fmaf(wr[q * 4 + 0], nv.x, h1[k]);
                h1[k] = fmaf(wr[q * 4 + 1], nv.y, h1[k]);
                h1[k] = fmaf(wr[q * 4 + 2], nv.z, h1[k]);
                h1[k] = fmaf(wr[q * 4 + 3], nv.w, h1[k]);
            }
        }
    }
#pragma unroll
    for (int k = 0; k < KNN; k++)
        h1s[(g * KNN + k) * 64 + t] = mishf(fmaf(h1[k], s1, t1));
    __syncthreads();

    float h2[KNN];
#pragma unroll
    for (int k = 0; k < KNN; k++) h2[k] = 0.f;
#pragma unroll
    for (int cb = 0; cb < 4; cb++) {
        float wr[16];
#pragma unroll
        for (int c = 0; c < 16; c++) wr[c] = w4T[(cb * 16 + c) * 64 + t];
#pragma unroll
        for (int k = 0; k < KNN; k++) {
            const float4* hp = (const float4*)&h1s[(g * KNN + k) * 64 + cb * 16];
#pragma unroll
            for (int q = 0; q < 4; q++) {
                float4 hv = hp[q];
                h2[k] = fmaf(wr[q * 4 + 0], hv.x, h2[k]);
                h2[k] = fmaf(wr[q * 4 + 1], hv.y, h2[k]);
                h2[k] = fmaf(wr[q * 4 + 2], hv.z, h2[k]);
                h2[k] = fmaf(wr[q * 4 + 3], hv.w, h2[k]);
            }
        }
    }
    float mx = -INFINITY;
#pragma unroll
    for (int k = 0; k < KNN; k++) mx = fmaxf(mx, mishf(fmaf(h2[k], s2, t2)));
    cat_store(b, 64 + t, i, mx);
    g_x2pm[((size_t)b * NPT + i) * 64 + t] = mx;
}

// ---------------- edge conv stage 3 (128 -> 64, max over K) ---------------
__global__ void edge3_kernel(const float* __restrict__ w5,
                             const float* __restrict__ g15, const float* __restrict__ b15,
                             const float* __restrict__ m15, const float* __restrict__ v15)
{
    __shared__ float w5T[128 * 64];
    __shared__ float ctr[4][64];
    __shared__ float nb[4][KNN][64];
    int tid = threadIdx.x;
    int g = tid >> 6, t = tid & 63;
    int b = blockIdx.y;
    int i = blockIdx.x * 4 + g;
    for (int l = tid; l < 8192; l += 256) { int o = l >> 7, c = l & 127; w5T[c * 64 + o] = w5[l]; }
    const int* idxp = &g_idx[(b * NPT + i) * KNN];
    ctr[g][t] = g_x2pm[((size_t)b * NPT + i) * 64 + t];
    int jn[KNN];
#pragma unroll
    for (int k = 0; k < KNN; k++) jn[k] = idxp[k];
#pragma unroll
    for (int k = 0; k < KNN; k++)
        nb[g][k][t] = g_x2pm[((size_t)b * NPT + jn[k]) * 64 + t];
    float s1 = g15[256 + t] * rsqrtf(v15[256 + t] + EPS);
    float t1 = b15[256 + t] - m15[256 + t] * s1;
    __syncthreads();

    float base = 0.f;
    for (int c = 0; c < 64; c++)
        base += (w5T[(64 + c) * 64 + t] - w5T[c * 64 + t]) * ctr[g][c];
    float h1[KNN];
#pragma unroll
    for (int k = 0; k < KNN; k++) h1[k] = base;
#pragma unroll
    for (int cb = 0; cb < 4; cb++) {
        float wr[16];
#pragma unroll
        for (int c = 0; c < 16; c++) wr[c] = w5T[(cb * 16 + c) * 64 + t];
#pragma unroll
        for (int k = 0; k < KNN; k++) {
            const float4* np = (const float4*)&nb[g][k][cb * 16];
#pragma unroll
            for (int q = 0; q < 4; q++) {
                float4 nv = np[q];
                h1[k] = fmaf(wr[q * 4 + 0], nv.x, h1[k]);
                h1[k] = fmaf(wr[q * 4 + 1], nv.y, h1[k]);
                h1[k] = fmaf(wr[q * 4 + 2], nv.z, h1[k]);
                h1[k] = fmaf(wr[q * 4 + 3], nv.w, h1[k]);
            }
        }
    }
    float mx = -INFINITY;
#pragma unroll
    for (int k = 0; k < KNN; k++) mx = fmaxf(mx, mishf(fmaf(h1[k], s1, t1)));
    cat_store(b, 128 + t, i, mx);
}

// ---------------- glob init -------------------------------------------------
__global__ void glob_init_kernel() {
    int p = blockIdx.x * blockDim.x + threadIdx.x;
    if (p < B * 1024) g_glob_i[p] = f2ord(-INFINITY);
}

// ---------------- tensor-core GEMM (pre-converted tf32 hi/lo) --------------
#define TCBM 128
#define TCBN 64
#define TCBK 16

__device__ __forceinline__ void mma_tf32(float c[4], const unsigned a[4], const unsigned b2[2]) {
    asm volatile(
        "mma.sync.aligned.m16n8k8.row.col.f32.tf32.tf32.f32 "
        "{%0,%1,%2,%3}, {%4,%5,%6,%7}, {%8,%9}, {%0,%1,%2,%3};"
        : "+f"(c[0]), "+f"(c[1]), "+f"(c[2]), "+f"(c[3])
        : "r"(a[0]), "r"(a[1]), "r"(a[2]), "r"(a[3]), "r"(b2[0]), "r"(b2[1]));
}

// xsel: 0 = cat(192)  2 = h7(512).  ysel: 0 = glob max  1 = h7 hi/lo  2 = h8 float
__global__ void gemm_tc_kernel(int wOff, int M, int Kd, int xsel, int ysel, int use_bias,
                               const float* __restrict__ gg, const float* __restrict__ bb,
                               const float* __restrict__ mm_, const float* __restrict__ vv)
{
    __shared__ unsigned Ah[TCBM][TCBK + 4];
    __shared__ unsigned Al[TCBM][TCBK + 4];
    __shared__ unsigned Bh[TCBK][TCBN + 4];
    __shared__ unsigned Bl[TCBK][TCBN + 4];

    int tid = threadIdx.x;
    int lane = tid & 31, wid = tid >> 5;
    int gid = lane >> 2, tig = lane & 3;
    int wm = wid >> 1, wn = wid & 1;

    int p0 = blockIdx.x * TCBN;
    int m0 = blockIdx.y * TCBM;
    int b = p0 / NPT, n0 = p0 % NPT;

    const unsigned* XbH = (xsel == 0) ? g_cat_h : g_h7h;
    const unsigned* XbL = (xsel == 0) ? g_cat_l : g_h7l;
    int xbs = (xsel == 0) ? 192 * NPT : 512 * NPT;

    float acc[4][4][4];
#pragma unroll
    for (int i = 0; i < 4; i++)
#pragma unroll
        for (int j = 0; j < 4; j++)
#pragma unroll
            for (int q = 0; q < 4; q++) acc[i][j][q] = 0.f;

    int nTiles = Kd / TCBK;
    uint4 aH[4], aL[4], bH[2], bL[2];

    auto loadT = [&](int kt) {
        int k0 = kt * TCBK;
#pragma unroll
        for (int i = 0; i < 4; i++) {
            int idx = tid + 128 * i;
            int m = idx >> 2, k4 = (idx & 3) * 4;
            size_t o = (size_t)wOff + (size_t)(m0 + m) * Kd + k0 + k4;
            aH[i] = *(const uint4*)&g_wh[o];
            aL[i] = *(const uint4*)&g_wl[o];
        }
#pragma unroll
        for (int i = 0; i < 2; i++) {
            int idx = tid + 128 * i;
            int k = idx >> 4, n4 = (idx & 15) * 4;
            size_t o = (size_t)b * xbs + (size_t)(k0 + k) * NPT + n0 + n4;
            bH[i] = *(const uint4*)&XbH[o];
            bL[i] = *(const uint4*)&XbL[o];
        }
    };
    auto storeT = [&]() {
#pragma unroll
        for (int i = 0; i < 4; i++) {
            int idx = tid + 128 * i;
            int m = idx >> 2, k4 = (idx & 3) * 4;
            *(uint4*)&Ah[m][k4] = aH[i];
            *(uint4*)&Al[m][k4] = aL[i];
        }
#pragma unroll
        for (int i = 0; i < 2; i++) {
            int idx = tid + 128 * i;
            int k = idx >> 4, n4 = (idx & 15) * 4;
            *(uint4*)&Bh[k][n4] = bH[i];
            *(uint4*)&Bl[k][n4] = bL[i];
        }
    };

    loadT(0);
    storeT();
    __syncthreads();

    for (int kt = 0; kt < nTiles; kt++) {
        if (kt + 1 < nTiles) loadT(kt + 1);
#pragma unroll
        for (int ks = 0; ks < 2; ks++) {
            int ko = ks * 8;
            unsigned ah[4][4], al[4][4], bh2[4][2], bl2[4][2];
#pragma unroll
            for (int mf = 0; mf < 4; mf++) {
                int r = wm * 64 + mf * 16 + gid;
                ah[mf][0] = Ah[r][ko + tig];     ah[mf][1] = Ah[r + 8][ko + tig];
                ah[mf][2] = Ah[r][ko + tig + 4]; ah[mf][3] = Ah[r + 8][ko + tig + 4];
                al[mf][0] = Al[r][ko + tig];     al[mf][1] = Al[r + 8][ko + tig];
                al[mf][2] = Al[r][ko + tig + 4]; al[mf][3] = Al[r + 8][ko + tig + 4];
            }
#pragma unroll
            for (int nf = 0; nf < 4; nf++) {
                int c = wn * 32 + nf * 8 + gid;
                bh2[nf][0] = Bh[ko + tig][c]; bh2[nf][1] = Bh[ko + tig + 4][c];
                bl2[nf][0] = Bl[ko + tig][c]; bl2[nf][1] = Bl[ko + tig + 4][c];
            }
#pragma unroll
            for (int mf = 0; mf < 4; mf++)
#pragma unroll
                for (int nf = 0; nf < 4; nf++) {
                    mma_tf32(acc[mf][nf], ah[mf], bh2[nf]);
                    mma_tf32(acc[mf][nf], ah[mf], bl2[nf]);
                    mma_tf32(acc[mf][nf], al[mf], bh2[nf]);
                }
        }
        __syncthreads();
        if (kt + 1 < nTiles) {
            storeT();
            __syncthreads();
        }
    }

    // --- epilogue ---
#pragma unroll
    for (int mf = 0; mf < 4; mf++) {
        int r0 = m0 + wm * 64 + mf * 16 + gid;
        int r1 = r0 + 8;
        float s0 = gg[r0] * rsqrtf(vv[r0] + EPS);
        float t0 = bb[r0] - mm_[r0] * s0;
        float s1 = gg[r1] * rsqrtf(vv[r1] + EPS);
        float t1 = bb[r1] - mm_[r1] * s1;
        float bv0 = use_bias ? g_bias7[b * M + r0] : 0.f;
        float bv1 = use_bias ? g_bias7[b * M + r1] : 0.f;
        if (ysel == 0) {
            float mx0 = -INFINITY, mx1 = -INFINITY;
#pragma unroll
            for (int nf = 0; nf < 4; nf++) {
                mx0 = fmaxf(mx0, fmaxf(mishf(fmaf(acc[mf][nf][0], s0, t0)),
                                       mishf(fmaf(acc[mf][nf][1], s0, t0))));
                mx1 = fmaxf(mx1, fmaxf(mishf(fmaf(acc[mf][nf][2], s1, t1)),
                                       mishf(fmaf(acc[mf][nf][3], s1, t1))));
            }
            mx0 = fmaxf(mx0, __shfl_xor_sync(0xffffffffu, mx0, 1));
            mx0 = fmaxf(mx0, __shfl_xor_sync(0xffffffffu, mx0, 2));
            mx1 = fmaxf(mx1, __shfl_xor_sync(0xffffffffu, mx1, 1));
            mx1 = fmaxf(mx1, __shfl_xor_sync(0xffffffffu, mx1, 2));
            if (tig == 0) {
                atomicMax(&g_glob_i[b * 1024 + r0], f2ord(mx0));
                atomicMax(&g_glob_i[b * 1024 + r1], f2ord(mx1));
            }
        } else if (ysel == 1) {
#pragma unroll
            for (int nf = 0; nf < 4; nf++) {
                int ncol = n0 + wn * 32 + nf * 8 + 2 * tig;
                float vs[4];
                vs[0] = mishf(fmaf(acc[mf][nf][0] + bv0, s0, t0));
                vs[1] = mishf(fmaf(acc[mf][nf][1] + bv0, s0, t0));
                vs[2] = mishf(fmaf(acc[mf][nf][2] + bv1, s1, t1));
                vs[3] = mishf(fmaf(acc[mf][nf][3] + bv1, s1, t1));
                unsigned hh[4], ll[4];
#pragma unroll
                for (int q = 0; q < 4; q++) {
                    hh[q] = f2tf32(vs[q]);
                    ll[q] = f2tf32(vs[q] - __uint_as_float(hh[q]));
                }
                size_t o0 = ((size_t)b * M + r0) * NPT + ncol;
                size_t o1 = ((size_t)b * M + r1) * NPT + ncol;
                *(uint2*)&g_h7h[o0] = make_uint2(hh[0], hh[1]);
                *(uint2*)&g_h7l[o0] = make_uint2(ll[0], ll[1]);
                *(uint2*)&g_h7h[o1] = make_uint2(hh[2], hh[3]);
                *(uint2*)&g_h7l[o1] = make_uint2(ll[2], ll[3]);
            }
        } else {
#pragma unroll
            for (int nf = 0; nf < 4; nf++) {
                int ncol = n0 + wn * 32 + nf * 8 + 2 * tig;
                float2 v0, v1;
                v0.x = mishf(fmaf(acc[mf][nf][0], s0, t0));
                v0.y = mishf(fmaf(acc[mf][nf][1], s0, t0));
                v1.x = mishf(fmaf(acc[mf][nf][2], s1, t1));
                v1.y = mishf(fmaf(acc[mf][nf][3], s1, t1));
                *(float2*)&g_h8[((size_t)b * M + r0) * NPT + ncol] = v0;
                *(float2*)&g_h8[((size_t)b * M + r1) * NPT + ncol] = v1;
            }
        }
    }
}

// ---------------- gemv: bias7[b,m] = w7[m, :1024] @ glob[b] ----------------
__global__ void gemv7_kernel(const float* __restrict__ w7) {
    int gw = (blockIdx.x * blockDim.x + threadIdx.x) >> 5;
    int lane = threadIdx.x & 31;
    if (gw >= B * 512) return;
    int b = gw / 512, m = gw % 512;
    const float* wr = w7 + (size_t)m * 1216;
    const int* gi = g_glob_i + b * 1024;
    float s = 0.f;
    for (int k = lane; k < 1024; k += 32)
        s = fmaf(wr[k], ord2f(gi[k]), s);
#pragma unroll
    for (int sh = 16; sh > 0; sh >>= 1) s += __shfl_xor_sync(0xffffffffu, s, sh);
    if (lane == 0) g_bias7[gw] = s;
}

// ---------------- dedicated w9 GEMM (18 x 256, no act) ---------------------
__global__ void w9_kernel(const float* __restrict__ W, float* __restrict__ out) {
    __shared__ float wsT[256][24];   // [k][m], 18 used, pad 24 (16B-aligned rows)
    int tid = threadIdx.x;
    for (int l = tid; l < 18 * 256; l += 256) {
        int m = l / 256, k = l % 256;
        wsT[k][m] = W[l];
    }
    __syncthreads();
    int p = blockIdx.x * 256 + tid;
    int b = p / NPT, n = p % NPT;
    float acc[18];
#pragma unroll
    for (int m = 0; m < 18; m++) acc[m] = 0.f;
    const float* xb = g_h8 + (size_t)b * 256 * NPT + n;
    for (int k = 0; k < 256; k++) {
        float xv = xb[(size_t)k * NPT];
        const float4* wp = (const float4*)&wsT[k][0];
#pragma unroll
        for (int q = 0; q < 4; q++) {
            float4 wv = wp[q];
            acc[q * 4 + 0] = fmaf(wv.x, xv, acc[q * 4 + 0]);
            acc[q * 4 + 1] = fmaf(wv.y, xv, acc[q * 4 + 1]);
            acc[q * 4 + 2] = fmaf(wv.z, xv, acc[q * 4 + 2]);
            acc[q * 4 + 3] = fmaf(wv.w, xv, acc[q * 4 + 3]);
        }
        float2 wv2 = *(const float2*)&wsT[k][16];
        acc[16] = fmaf(wv2.x, xv, acc[16]);
        acc[17] = fmaf(wv2.y, xv, acc[17]);
    }
    float* op = out + (size_t)b * 18 * NPT + n;
#pragma unroll
    for (int m = 0; m < 18; m++) op[(size_t)m * NPT] = acc[m];
}

// ---------------- launch ---------------------------------------------------
extern "C" void kernel_launch(void* const* d_in, const int* in_sizes, int n_in,
                              void* d_out, int out_size)
{
    const float* x   = (const float*)d_in[0];
    const float* w1  = (const float*)d_in[1];
    const float* w2  = (const float*)d_in[2];
    const float* w3  = (const float*)d_in[3];
    const float* w4  = (const float*)d_in[4];
    const float* w5  = (const float*)d_in[5];
    const float* w6  = (const float*)d_in[6];
    const float* w7  = (const float*)d_in[7];
    const float* w8  = (const float*)d_in[8];
    const float* w9  = (const float*)d_in[9];
    const float* g15 = (const float*)d_in[10];
    const float* b15 = (const float*)d_in[11];
    const float* m15 = (const float*)d_in[12];
    const float* v15 = (const float*)d_in[13];
    const float* g6  = (const float*)d_in[14];
    const float* b6  = (const float*)d_in[15];
    const float* m6  = (const float*)d_in[16];
    const float* v6  = (const float*)d_in[17];
    const float* g7  = (const float*)d_in[18];
    const float* b7  = (const float*)d_in[19];
    const float* m7  = (const float*)d_in[20];
    const float* v7  = (const float*)d_in[21];
    const float* g8  = (const float*)d_in[22];
    const float* b8  = (const float*)d_in[23];
    const float* m8  = (const float*)d_in[24];
    const float* v8  = (const float*)d_in[25];
    float* out = (float*)d_out;

    cudaFuncSetAttribute(edge2_kernel, cudaFuncAttributeMaxDynamicSharedMemorySize, 70656);
    cudaFuncSetAttribute(knn_kernel<3, 8>, cudaFuncAttributeMaxDynamicSharedMemorySize, 73728);
    cudaFuncSetAttribute(knn_kernel<64, 8>, cudaFuncAttributeMaxDynamicSharedMemorySize, 73728);

    dim3 eg(NPT / 4, B);
    dim3 kg(NPT / 8, B);
    int sqb = (B * NPT + 255) / 256;
    size_t ksm3  = 8 * 3 * 8  + 8 * NPT * 4;   // u64 queries + float s_neg
    size_t ksm64 = 8 * 64 * 8 + 8 * NPT * 4;

    // weight pre-conversion (independent of data path)
    convw_kernel<<<(1024 * 192 + 255) / 256, 256>>>(w6, 192, 0, 0, 1024, 192);
    convw_kernel<<<(512 * 192 + 255) / 256, 256>>>(w7, 1216, 1024, 196608, 512, 192);
    convw_kernel<<<(256 * 512 + 255) / 256, 256>>>(w8, 512, 0, 294912, 256, 512);
    glob_init_kernel<<<(B * 1024 + 255) / 256, 256>>>();

    // stage 1
    sq_kernel<3><<<sqb, 256>>>(x, 0);
    knn_kernel<3, 8><<<kg, 256, ksm3>>>(x, 0);
    edge1_kernel<<<eg, 256>>>(x, w1, w2, g15, b15, m15, v15);

    // stage 2
    sq_kernel<64><<<sqb, 256>>>(nullptr, 0);
    knn_kernel<64, 8><<<kg, 256, ksm64>>>(nullptr, 0);
    edge2_kernel<<<eg, 256, 70656>>>(w3, w4, g15, b15, m15, v15);

    // stage 3
    sq_kernel<64><<<sqb, 256>>>(nullptr, 64);
    knn_kernel<64, 8><<<kg, 256, ksm64>>>(nullptr, 64);
    edge3_kernel<<<eg, 256>>>(w5, g15, b15, m15, v15);

    // dense layers
    gemm_tc_kernel<<<dim3(B * NPT / TCBN, 8), 128>>>(0, 1024, 192, 0, 0, 0,
                                                     g6, b6, m6, v6);
    gemv7_kernel<<<(B * 512) / 8, 256>>>(w7);
    gemm_tc_kernel<<<dim3(B * NPT / TCBN, 4), 128>>>(196608, 512, 192, 0, 1, 1,
                                                     g7, b7, m7, v7);
    gemm_tc_kernel<<<dim3(B * NPT / TCBN, 2), 128>>>(294912, 256, 512, 2, 2, 0,
                                                     g8, b8, m8, v8);
    w9_kernel<<<B * NPT / 256, 256>>>(w9, out);
}

// round 12
// speedup vs baseline: 1.0027x; 1.0027x over previous
#include <cuda_runtime.h>
#include <math.h>

#define B   8
#define NPT 2048
#define KNN 10
#define EPS 1e-5f

// ---------------- scratch (device globals; referenced from DEVICE code only)
__device__ float    g_cat  [B * 192 * NPT];
__device__ unsigned g_cat_h[B * 192 * NPT];
__device__ unsigned g_cat_l[B * 192 * NPT];
__device__ float    g_x1pm [B * NPT * 64];   // point-major x1 (for edge2 gather)
__device__ float    g_x2pm [B * NPT * 64];   // point-major x2 (for edge3 gather)
__device__ float    g_sq [B * NPT];
__device__ int      g_idx[B * NPT * KNN];
__device__ int      g_glob_i[B * 1024];
__device__ float    g_bias7[B * 512];
__device__ unsigned g_h7h[B * 512 * NPT];
__device__ unsigned g_h7l[B * 512 * NPT];
__device__ float    g_h8 [B * 256 * NPT];
__device__ unsigned g_wh[425984];
__device__ unsigned g_wl[425984];

// fast mish: tanh(softplus(x)) = u/(u+2), u = t(t+2), t = e^x
__device__ __forceinline__ float mishf(float x) {
    float t = expf(x);
    float u = t * (t + 2.f);
    float r = x * u / (u + 2.f);
    return (x > 20.f) ? x : r;
}
__device__ __forceinline__ unsigned f2tf32(float x) {
    unsigned r; asm("cvt.rna.tf32.f32 %0, %1;" : "=r"(r) : "f"(x)); return r;
}
__device__ __forceinline__ int f2ord(float f) {
    int i = __float_as_int(f); return (i >= 0) ? i : (i ^ 0x7fffffff);
}
__device__ __forceinline__ float ord2f(int o) {
    return __int_as_float((o >= 0) ? o : (o ^ 0x7fffffff));
}
__device__ __forceinline__ unsigned long long pack2(float x, float y) {
    unsigned long long r;
    asm("mov.b64 %0, {%1, %2};" : "=l"(r) : "f"(x), "f"(y));
    return r;
}
__device__ __forceinline__ void unpack2(unsigned long long v, float& lo, float& hi) {
    asm("mov.b64 {%0, %1}, %2;" : "=f"(lo), "=f"(hi) : "l"(v));
}
__device__ __forceinline__ void ffma2(unsigned long long& acc,
                                      unsigned long long a, unsigned long long b) {
    asm("fma.rn.f32x2 %0, %1, %2, %0;" : "+l"(acc) : "l"(a), "l"(b));
}

// ---------------- weight pre-conversion to tf32 hi/lo ----------------------
__global__ void convw_kernel(const float* __restrict__ w, int srcLd, int srcOff,
                             int dstOff, int M, int Kd) {
    int i = blockIdx.x * blockDim.x + threadIdx.x;
    if (i >= M * Kd) return;
    int m = i / Kd, k = i % Kd;
    float x = w[(size_t)m * srcLd + srcOff + k];
    unsigned h = f2tf32(x);
    g_wh[dstOff + i] = h;
    g_wl[dstOff + i] = f2tf32(x - __uint_as_float(h));
}

// ---------------- squared norms --------------------------------------------
template<int C>
__global__ void sq_kernel(const float* __restrict__ Xext, int chanOff) {
    int p = blockIdx.x * blockDim.x + threadIdx.x;
    if (p >= B * NPT) return;
    int b = p / NPT, n = p % NPT;
    const float* xp = (C == 3) ? (Xext + b * 3 * NPT + n)
                               : (g_cat + b * 192 * NPT + chanOff * NPT + n);
    float s = 0.f;
#pragma unroll
    for (int c = 0; c < C; c++) { float v = xp[c * NPT]; s = fmaf(v, v, s); }
    g_sq[p] = s;
}

// ---------------- kNN: packed-f32x2 distances + warp-local top-10 ----------
template<int C, int IT>
__global__ void knn_kernel(const float* __restrict__ Xext, int chanOff) {
    extern __shared__ unsigned long long sm64[];
    unsigned long long* s_xi2 = sm64;                  // IT*C (query dup-packed)
    float* s_neg = (float*)(sm64 + IT * C);            // IT*NPT

    int b = blockIdx.y, i0 = blockIdx.x * IT, tid = threadIdx.x;
    int lane = tid & 31, w = tid >> 5;
    const float* Xb = (C == 3) ? (Xext + b * 3 * NPT)
                               : (g_cat + b * 192 * NPT + chanOff * NPT);
    for (int l = tid; l < IT * C; l += 256) {
        int ii = l / C, c = l % C;
        float v = Xb[c * NPT + i0 + ii];
        s_xi2[ii * C + c] = pack2(v, v);
    }
    __syncthreads();
    float sqi[IT];
#pragma unroll
    for (int ii = 0; ii < IT; ii++) sqi[ii] = g_sq[b * NPT + i0 + ii];

    // distance: thread handles 2 consecutive keys per block-iter (f32x2 fma)
#pragma unroll
    for (int jb = 0; jb < NPT / 512; jb++) {
        int j0 = jb * 512 + tid * 2;
        unsigned long long acc2[IT];
#pragma unroll
        for (int ii = 0; ii < IT; ii++) acc2[ii] = 0ull;
        for (int c = 0; c < C; c++) {
            unsigned long long kv = *(const unsigned long long*)&Xb[c * NPT + j0];
#pragma unroll
            for (int ii = 0; ii < IT; ii++) {
                unsigned long long q = s_xi2[ii * C + c];
                ffma2(acc2[ii], kv, q);
            }
        }
        float2 sqj = *(const float2*)&g_sq[b * NPT + j0];
#pragma unroll
        for (int ii = 0; ii < IT; ii++) {
            float a0, a1; unpack2(acc2[ii], a0, a1);
            float2 o;
            o.x = 2.f * a0 - sqi[ii] - sqj.x;
            o.y = 2.f * a1 - sqi[ii] - sqj.y;
            *(float2*)&s_neg[ii * NPT + j0] = o;
        }
    }
    __syncthreads();

    // --- warp-local top-K for point w (lane owns stripe j%32==lane) ---
    float* neg = s_neg + w * NPT;
    float v = -INFINITY; int id = NPT;
#pragma unroll 8
    for (int i = 0; i < NPT / 32; i++) {
        int j = lane + 32 * i;
        float nv = neg[j];
        if (nv > v) { v = nv; id = j; }       // ascending j: ties keep lowest idx
    }
    int* op = &g_idx[(b * NPT + i0 + w) * KNN];
    for (int r = 0; r < KNN; r++) {
        float bv = v; int bi = id;
#pragma unroll
        for (int s = 16; s > 0; s >>= 1) {
            float ov = __shfl_xor_sync(0xffffffffu, bv, s);
            int   oi = __shfl_xor_sync(0xffffffffu, bi, s);
            if (ov > bv || (ov == bv && oi < bi)) { bv = ov; bi = oi; }
        }
        if (lane == 0) op[r] = bi;
        if ((bi & 31) == lane) {
            neg[bi] = -INFINITY;
            v = -INFINITY; id = NPT;
            for (int i = 0; i < NPT / 32; i++) {
                int j = lane + 32 * i;
                float nv = neg[j];
                if (nv > v) { v = nv; id = j; }
            }
        }
    }
}

// ---------------- cat writer (float + tf32 hi/lo mirrors) ------------------
__device__ __forceinline__ void cat_store(int b, int ch, int i, float v) {
    size_t o = (size_t)b * 192 * NPT + (size_t)ch * NPT + i;
    g_cat[o] = v;
    unsigned h = f2tf32(v);
    g_cat_h[o] = h;
    g_cat_l[o] = f2tf32(v - __uint_as_float(h));
}

// ---------------- edge conv stage 1 (6 -> 64 -> 64, max over K) -----------
__global__ void edge1_kernel(const float* __restrict__ X,
                             const float* __restrict__ w1, const float* __restrict__ w2,
                             const float* __restrict__ g15, const float* __restrict__ b15,
                             const float* __restrict__ m15, const float* __restrict__ v15)
{
    __shared__ float w1T[6 * 64];
    __shared__ float w2T[64 * 64];
    __shared__ float ctr[4][4];
    __shared__ float nb[4][KNN][4];
    __shared__ float h1s[4][KNN][64];
    int tid = threadIdx.x;
    int g = tid >> 6, t = tid & 63;
    int b = blockIdx.y;
    int i = blockIdx.x * 4 + g;
    for (int l = tid; l < 384; l += 256) { int o = l / 6, c = l % 6; w1T[c * 64 + o] = w1[l]; }
    for (int l = tid; l < 4096; l += 256) { int o = l >> 6, c = l & 63; w2T[c * 64 + o] = w2[l]; }
    const int* idxp = &g_idx[(b * NPT + i) * KNN];
    if (t < 3) ctr[g][t] = X[b * 3 * NPT + t * NPT + i];
    if (t < 30) {
        int k = t / 3, c = t % 3;
        nb[g][k][c] = X[b * 3 * NPT + c * NPT + idxp[k]];
    }
    float s1 = g15[t] * rsqrtf(v15[t] + EPS);
    float t1 = b15[t] - m15[t] * s1;
    float s2 = g15[64 + t] * rsqrtf(v15[64 + t] + EPS);
    float t2 = b15[64 + t] - m15[64 + t] * s2;
    __syncthreads();

    float base = 0.f;
#pragma unroll
    for (int c = 0; c < 3; c++)
        base += (w1T[(3 + c) * 64 + t] - w1T[c * 64 + t]) * ctr[g][c];
#pragma unroll
    for (int k = 0; k < KNN; k++) {
        float h = base;
#pragma unroll
        for (int c = 0; c < 3; c++) h = fmaf(w1T[c * 64 + t], nb[g][k][c], h);
        h1s[g][k][t] = mishf(fmaf(h, s1, t1));
    }
    __syncthreads();

    float h2[KNN];
#pragma unroll
    for (int k = 0; k < KNN; k++) h2[k] = 0.f;
#pragma unroll
    for (int cb = 0; cb < 4; cb++) {
        float wr[16];
#pragma unroll
        for (int c = 0; c < 16; c++) wr[c] = w2T[(cb * 16 + c) * 64 + t];
#pragma unroll
        for (int k = 0; k < KNN; k++) {
            const float4* hp = (const float4*)&h1s[g][k][cb * 16];
#pragma unroll
            for (int q = 0; q < 4; q++) {
                float4 hv = hp[q];
                h2[k] = fmaf(wr[q * 4 + 0], hv.x, h2[k]);
                h2[k] = fmaf(wr[q * 4 + 1], hv.y, h2[k]);
                h2[k] = fmaf(wr[q * 4 + 2], hv.z, h2[k]);
                h2[k] = fmaf(wr[q * 4 + 3], hv.w, h2[k]);
            }
        }
    }
    float mx = -INFINITY;
#pragma unroll
    for (int k = 0; k < KNN; k++) mx = fmaxf(mx, mishf(fmaf(h2[k], s2, t2)));
    cat_store(b, t, i, mx);
    g_x1pm[((size_t)b * NPT + i) * 64 + t] = mx;
}

// ---------------- edge conv stage 2 (128 -> 64 -> 64, max over K) ---------
extern __shared__ float dsm2[];
__global__ void edge2_kernel(const float* __restrict__ w3, const float* __restrict__ w4,
                             const float* __restrict__ g15, const float* __restrict__ b15,
                             const float* __restrict__ m15, const float* __restrict__ v15)
{
    float* w3T = dsm2;                        // 8192
    float* w4T = dsm2 + 8192;                 // 4096
    float* ctr = dsm2 + 12288;                // 4*64
    float* nb  = dsm2 + 12544;                // 4*10*64
    float* h1s = dsm2 + 15104;                // 4*10*64
    int tid = threadIdx.x;
    int g = tid >> 6, t = tid & 63;
    int b = blockIdx.y;
    int i = blockIdx.x * 4 + g;
    for (int l = tid; l < 8192; l += 256) { int o = l >> 7, c = l & 127; w3T[c * 64 + o] = w3[l]; }
    for (int l = tid; l < 4096; l += 256) { int o = l >> 6, c = l & 63;  w4T[c * 64 + o] = w4[l]; }
    const int* idxp = &g_idx[(b * NPT + i) * KNN];
    ctr[g * 64 + t] = g_x1pm[((size_t)b * NPT + i) * 64 + t];    // coalesced
    int jn[KNN];
#pragma unroll
    for (int k = 0; k < KNN; k++) jn[k] = idxp[k];
#pragma unroll
    for (int k = 0; k < KNN; k++)
        nb[(g * KNN + k) * 64 + t] = g_x1pm[((size_t)b * NPT + jn[k]) * 64 + t];  // coalesced
    float s1 = g15[128 + t] * rsqrtf(v15[128 + t] + EPS);
    float t1 = b15[128 + t] - m15[128 + t] * s1;
    float s2 = g15[192 + t] * rsqrtf(v15[192 + t] + EPS);
    float t2 = b15[192 + t] - m15[192 + t] * s2;
    __syncthreads();

    float base = 0.f;
    for (int c = 0; c < 64; c++)
        base += (w3T[(64 + c) * 64 + t] - w3T[c * 64 + t]) * ctr[g * 64 + c];
    float h1[KNN];
#pragma unroll
    for (int k = 0; k < KNN; k++) h1[k] = base;
#pragma unroll
    for (int cb = 0; cb < 4; cb++) {
        float wr[16];
#pragma unroll
        for (int c = 0; c < 16; c++) wr[c] = w3T[(cb * 16 + c) * 64 + t];
#pragma unroll
        for (int k = 0; k < KNN; k++) {
            const float4* np = (const float4*)&nb[(g * KNN + k) * 64 + cb * 16];
#pragma unroll
            for (int q = 0; q < 4; q++) {
                float4 nv = np[q];
                h1[k] = fmaf(wr[q * 4 + 0], nv.x, h1[k]);
                h1[k] = fmaf(wr[q * 4 + 1], nv.y, h1[k]);
                h1[k] = fmaf(wr[q * 4 + 2], nv.z, h1[k]);
                h1[k] = fmaf(wr[q * 4 + 3], nv.w, h1[k]);
            }
        }
    }
#pragma unroll
    for (int k = 0; k < KNN; k++)
        h1s[(g * KNN + k) * 64 + t] = mishf(fmaf(h1[k], s1, t1));
    __syncthreads();

    float h2[KNN];
#pragma unroll
    for (int k = 0; k < KNN; k++) h2[k] = 0.f;
#pragma unroll
    for (int cb = 0; cb < 4; cb++) {
        float wr[16];
#pragma unroll
        for (int c = 0; c < 16; c++) wr[c] = w4T[(cb * 16 + c) * 64 + t];
#pragma unroll
        for (int k = 0; k < KNN; k++) {
            const float4* hp = (const float4*)&h1s[(g * KNN + k) * 64 + cb * 16];
#pragma unroll
            for (int q = 0; q < 4; q++) {
                float4 hv = hp[q];
                h2[k] = fmaf(wr[q * 4 + 0], hv.x, h2[k]);
                h2[k] = fmaf(wr[q * 4 + 1], hv.y, h2[k]);
                h2[k] = fmaf(wr[q * 4 + 2], hv.z, h2[k]);
                h2[k] = fmaf(wr[q * 4 + 3], hv.w, h2[k]);
            }
        }
    }
    float mx = -INFINITY;
#pragma unroll
    for (int k = 0; k < KNN; k++) mx = fmaxf(mx, mishf(fmaf(h2[k], s2, t2)));
    cat_store(b, 64 + t, i, mx);
    g_x2pm[((size_t)b * NPT + i) * 64 + t] = mx;
}

// ---------------- edge conv stage 3 (128 -> 64, max over K) ---------------
__global__ void edge3_kernel(const float* __restrict__ w5,
                             const float* __restrict__ g15, const float* __restrict__ b15,
                             const float* __restrict__ m15, const float* __restrict__ v15)
{
    __shared__ float w5T[128 * 64];
    __shared__ float ctr[4][64];
    __shared__ float nb[4][KNN][64];
    int tid = threadIdx.x;
    int g = tid >> 6, t = tid & 63;
    int b = blockIdx.y;
    int i = blockIdx.x * 4 + g;
    for (int l = tid; l < 8192; l += 256) { int o = l >> 7, c = l & 127; w5T[c * 64 + o] = w5[l]; }
    const int* idxp = &g_idx[(b * NPT + i) * KNN];
    ctr[g][t] = g_x2pm[((size_t)b * NPT + i) * 64 + t];
    int jn[KNN];
#pragma unroll
    for (int k = 0; k < KNN; k++) jn[k] = idxp[k];
#pragma unroll
    for (int k = 0; k < KNN; k++)
        nb[g][k][t] = g_x2pm[((size_t)b * NPT + jn[k]) * 64 + t];
    float s1 = g15[256 + t] * rsqrtf(v15[256 + t] + EPS);
    float t1 = b15[256 + t] - m15[256 + t] * s1;
    __syncthreads();

    float base = 0.f;
    for (int c = 0; c < 64; c++)
        base += (w5T[(64 + c) * 64 + t] - w5T[c * 64 + t]) * ctr[g][c];
    float h1[KNN];
#pragma unroll
    for (int k = 0; k < KNN; k++) h1[k] = base;
#pragma unroll
    for (int cb = 0; cb < 4; cb++) {
        float wr[16];
#pragma unroll
        for (int c = 0; c < 16; c++) wr[c] = w5T[(cb * 16 + c) * 64 + t];
#pragma unroll
        for (int k = 0; k < KNN; k++) {
            const float4* np = (const float4*)&nb[g][k][cb * 16];
#pragma unroll
            for (int q = 0; q < 4; q++) {
                float4 nv = np[q];
                h1[k] = fmaf(wr[q * 4 + 0], nv.x, h1[k]);
                h1[k] = fmaf(wr[q * 4 + 1], nv.y, h1[k]);
                h1[k] = fmaf(wr[q * 4 + 2], nv.z, h1[k]);
                h1[k] = fmaf(wr[q * 4 + 3], nv.w, h1[k]);
            }
        }
    }
    float mx = -INFINITY;
#pragma unroll
    for (int k = 0; k < KNN; k++) mx = fmaxf(mx, mishf(fmaf(h1[k], s1, t1)));
    cat_store(b, 128 + t, i, mx);
}

// ---------------- glob init -------------------------------------------------
__global__ void glob_init_kernel() {
    int p = blockIdx.x * blockDim.x + threadIdx.x;
    if (p < B * 1024) g_glob_i[p] = f2ord(-INFINITY);
}

// ---------------- tensor-core GEMM (pre-converted tf32 hi/lo) --------------
#define TCBM 128
#define TCBN 64
#define TCBK 16

__device__ __forceinline__ void mma_tf32(float c[4], const unsigned a[4], const unsigned b2[2]) {
    asm volatile(
        "mma.sync.aligned.m16n8k8.row.col.f32.tf32.tf32.f32 "
        "{%0,%1,%2,%3}, {%4,%5,%6,%7}, {%8,%9}, {%0,%1,%2,%3};"
        : "+f"(c[0]), "+f"(c[1]), "+f"(c[2]), "+f"(c[3])
        : "r"(a[0]), "r"(a[1]), "r"(a[2]), "r"(a[3]), "r"(b2[0]), "r"(b2[1]));
}

// xsel: 0 = cat(192)  2 = h7(512).  ysel: 0 = glob max  1 = h7 hi/lo  2 = h8 float
__global__ void gemm_tc_kernel(int wOff, int M, int Kd, int xsel, int ysel, int use_bias,
                               const float* __restrict__ gg, const float* __restrict__ bb,
                               const float* __restrict__ mm_, const float* __restrict__ vv)
{
    __shared__ unsigned Ah[TCBM][TCBK + 4];
    __shared__ unsigned Al[TCBM][TCBK + 4];
    __shared__ unsigned Bh[TCBK][TCBN + 4];
    __shared__ unsigned Bl[TCBK][TCBN + 4];

    int tid = threadIdx.x;
    int lane = tid & 31, wid = tid >> 5;
    int gid = lane >> 2, tig = lane & 3;
    int wm = wid >> 1, wn = wid & 1;

    int p0 = blockIdx.x * TCBN;
    int m0 = blockIdx.y * TCBM;
    int b = p0 / NPT, n0 = p0 % NPT;

    const unsigned* XbH = (xsel == 0) ? g_cat_h : g_h7h;
    const unsigned* XbL = (xsel == 0) ? g_cat_l : g_h7l;
    int xbs = (xsel == 0) ? 192 * NPT : 512 * NPT;

    float acc[4][4][4];
#pragma unroll
    for (int i = 0; i < 4; i++)
#pragma unroll
        for (int j = 0; j < 4; j++)
#pragma unroll
            for (int q = 0; q < 4; q++) acc[i][j][q] = 0.f;

    int nTiles = Kd / TCBK;
    uint4 aH[4], aL[4], bH[2], bL[2];

    auto loadT = [&](int kt) {
        int k0 = kt * TCBK;
#pragma unroll
        for (int i = 0; i < 4; i++) {
            int idx = tid + 128 * i;
            int m = idx >> 2, k4 = (idx & 3) * 4;
            size_t o = (size_t)wOff + (size_t)(m0 + m) * Kd + k0 + k4;
            aH[i] = *(const uint4*)&g_wh[o];
            aL[i] = *(const uint4*)&g_wl[o];
        }
#pragma unroll
        for (int i = 0; i < 2; i++) {
            int idx = tid + 128 * i;
            int k = idx >> 4, n4 = (idx & 15) * 4;
            size_t o = (size_t)b * xbs + (size_t)(k0 + k) * NPT + n0 + n4;
            bH[i] = *(const uint4*)&XbH[o];
            bL[i] = *(const uint4*)&XbL[o];
        }
    };
    auto storeT = [&]() {
#pragma unroll
        for (int i = 0; i < 4; i++) {
            int idx = tid + 128 * i;
            int m = idx >> 2, k4 = (idx & 3) * 4;
            *(uint4*)&Ah[m][k4] = aH[i];
            *(uint4*)&Al[m][k4] = aL[i];
        }
#pragma unroll
        for (int i = 0; i < 2; i++) {
            int idx = tid + 128 * i;
            int k = idx >> 4, n4 = (idx & 15) * 4;
            *(uint4*)&Bh[k][n4] = bH[i];
            *(uint4*)&Bl[k][n4] = bL[i];
        }
    };

    loadT(0);
    storeT();
    __syncthreads();

    for (int kt = 0; kt < nTiles; kt++) {
        if (kt + 1 < nTiles) loadT(kt + 1);
#pragma unroll
        for (int ks = 0; ks < 2; ks++) {
            int ko = ks * 8;
            unsigned ah[4][4], al[4][4], bh2[4][2], bl2[4][2];
#pragma unroll
            for (int mf = 0; mf < 4; mf++) {
                int r = wm * 64 + mf * 16 + gid;
                ah[mf][0] = Ah[r][ko + tig];     ah[mf][1] = Ah[r + 8][ko + tig];
                ah[mf][2] = Ah[r][ko + tig + 4]; ah[mf][3] = Ah[r + 8][ko + tig + 4];
                al[mf][0] = Al[r][ko + tig];     al[mf][1] = Al[r + 8][ko + tig];
                al[mf][2] = Al[r][ko + tig + 4]; al[mf][3] = Al[r + 8][ko + tig + 4];
            }
#pragma unroll
            for (int nf = 0; nf < 4; nf++) {
                int c = wn * 32 + nf * 8 + gid;
                bh2[nf][0] = Bh[ko + tig][c]; bh2[nf][1] = Bh[ko + tig + 4][c];
                bl2[nf][0] = Bl[ko + tig][c]; bl2[nf][1] = Bl[ko + tig + 4][c];
            }
#pragma unroll
            for (int mf = 0; mf < 4; mf++)
#pragma unroll
                for (int nf = 0; nf < 4; nf++) {
                    mma_tf32(acc[mf][nf], ah[mf], bh2[nf]);
                    mma_tf32(acc[mf][nf], ah[mf], bl2[nf]);
                    mma_tf32(acc[mf][nf], al[mf], bh2[nf]);
                }
        }
        __syncthreads();
        if (kt + 1 < nTiles) {
            storeT();
            __syncthreads();
        }
    }

    // --- epilogue ---
#pragma unroll
    for (int mf = 0; mf < 4; mf++) {
        int r0 = m0 + wm * 64 + mf * 16 + gid;
        int r1 = r0 + 8;
        float s0 = gg[r0] * rsqrtf(vv[r0] + EPS);
        float t0 = bb[r0] - mm_[r0] * s0;
        float s1 = gg[r1] * rsqrtf(vv[r1] + EPS);
        float t1 = bb[r1] - mm_[r1] * s1;
        float bv0 = use_bias ? g_bias7[b * M + r0] : 0.f;
        float bv1 = use_bias ? g_bias7[b * M + r1] : 0.f;
        if (ysel == 0) {
            float mx0 = -INFINITY, mx1 = -INFINITY;
#pragma unroll
            for (int nf = 0; nf < 4; nf++) {
                mx0 = fmaxf(mx0, fmaxf(mishf(fmaf(acc[mf][nf][0], s0, t0)),
                                       mishf(fmaf(acc[mf][nf][1], s0, t0))));
                mx1 = fmaxf(mx1, fmaxf(mishf(fmaf(acc[mf][nf][2], s1, t1)),
                                       mishf(fmaf(acc[mf][nf][3], s1, t1))));
            }
            mx0 = fmaxf(mx0, __shfl_xor_sync(0xffffffffu, mx0, 1));
            mx0 = fmaxf(mx0, __shfl_xor_sync(0xffffffffu, mx0, 2));
            mx1 = fmaxf(mx1, __shfl_xor_sync(0xffffffffu, mx1, 1));
            mx1 = fmaxf(mx1, __shfl_xor_sync(0xffffffffu, mx1, 2));
            if (tig == 0) {
                atomicMax(&g_glob_i[b * 1024 + r0], f2ord(mx0));
                atomicMax(&g_glob_i[b * 1024 + r1], f2ord(mx1));
            }
        } else if (ysel == 1) {
#pragma unroll
            for (int nf = 0; nf < 4; nf++) {
                int ncol = n0 + wn * 32 + nf * 8 + 2 * tig;
                float vs[4];
                vs[0] = mishf(fmaf(acc[mf][nf][0] + bv0, s0, t0));
                vs[1] = mishf(fmaf(acc[mf][nf][1] + bv0, s0, t0));
                vs[2] = mishf(fmaf(acc[mf][nf][2] + bv1, s1, t1));
                vs[3] = mishf(fmaf(acc[mf][nf][3] + bv1, s1, t1));
                unsigned hh[4], ll[4];
#pragma unroll
                for (int q = 0; q < 4; q++) {
                    hh[q] = f2tf32(vs[q]);
                    ll[q] = f2tf32(vs[q] - __uint_as_float(hh[q]));
                }
                size_t o0 = ((size_t)b * M + r0) * NPT + ncol;
                size_t o1 = ((size_t)b * M + r1) * NPT + ncol;
                *(uint2*)&g_h7h[o0] = make_uint2(hh[0], hh[1]);
                *(uint2*)&g_h7l[o0] = make_uint2(ll[0], ll[1]);
                *(uint2*)&g_h7h[o1] = make_uint2(hh[2], hh[3]);
                *(uint2*)&g_h7l[o1] = make_uint2(ll[2], ll[3]);
            }
        } else {
#pragma unroll
            for (int nf = 0; nf < 4; nf++) {
                int ncol = n0 + wn * 32 + nf * 8 + 2 * tig;
                float2 v0, v1;
                v0.x = mishf(fmaf(acc[mf][nf][0], s0, t0));
                v0.y = mishf(fmaf(acc[mf][nf][1], s0, t0));
                v1.x = mishf(fmaf(acc[mf][nf][2], s1, t1));
                v1.y = mishf(fmaf(acc[mf][nf][3], s1, t1));
                *(float2*)&g_h8[((size_t)b * M + r0) * NPT + ncol] = v0;
                *(float2*)&g_h8[((size_t)b * M + r1) * NPT + ncol] = v1;
            }
        }
    }
}

// ---------------- gemv: bias7[b,m] = w7[m, :1024] @ glob[b] ----------------
__global__ void gemv7_kernel(const float* __restrict__ w7) {
    int gw = (blockIdx.x * blockDim.x + threadIdx.x) >> 5;
    int lane = threadIdx.x & 31;
    if (gw >= B * 512) return;
    int b = gw / 512, m = gw % 512;
    const float* wr = w7 + (size_t)m * 1216;
    const int* gi = g_glob_i + b * 1024;
    float s = 0.f;
    for (int k = lane; k < 1024; k += 32)
        s = fmaf(wr[k], ord2f(gi[k]), s);
#pragma unroll
    for (int sh = 16; sh > 0; sh >>= 1) s += __shfl_xor_sync(0xffffffffu, s, sh);
    if (lane == 0) g_bias7[gw] = s;
}

// ---------------- dedicated w9 GEMM (18 x 256, no act) ---------------------
__global__ void w9_kernel(const float* __restrict__ W, float* __restrict__ out) {
    __shared__ float wsT[256][24];   // [k][m], 18 used, pad 24 (16B-aligned rows)
    int tid = threadIdx.x;
    for (int l = tid; l < 18 * 256; l += 256) {
        int m = l / 256, k = l % 256;
        wsT[k][m] = W[l];
    }
    __syncthreads();
    int p = blockIdx.x * 256 + tid;
    int b = p / NPT, n = p % NPT;
    float acc[18];
#pragma unroll
    for (int m = 0; m < 18; m++) acc[m] = 0.f;
    const float* xb = g_h8 + (size_t)b * 256 * NPT + n;
    for (int k = 0; k < 256; k++) {
        float xv = xb[(size_t)k * NPT];
        const float4* wp = (const float4*)&wsT[k][0];
#pragma unroll
        for (int q = 0; q < 4; q++) {
            float4 wv = wp[q];
            acc[q * 4 + 0] = fmaf(wv.x, xv, acc[q * 4 + 0]);
            acc[q * 4 + 1] = fmaf(wv.y, xv, acc[q * 4 + 1]);
            acc[q * 4 + 2] = fmaf(wv.z, xv, acc[q * 4 + 2]);
            acc[q * 4 + 3] = fmaf(wv.w, xv, acc[q * 4 + 3]);
        }
        float2 wv2 = *(const float2*)&wsT[k][16];
        acc[16] = fmaf(wv2.x, xv, acc[16]);
        acc[17] = fmaf(wv2.y, xv, acc[17]);
    }
    float* op = out + (size_t)b * 18 * NPT + n;
#pragma unroll
    for (int m = 0; m < 18; m++) op[(size_t)m * NPT] = acc[m];
}

// ---------------- launch ---------------------------------------------------
extern "C" void kernel_launch(void* const* d_in, const int* in_sizes, int n_in,
                              void* d_out, int out_size)
{
    const float* x   = (const float*)d_in[0];
    const float* w1  = (const float*)d_in[1];
    const float* w2  = (const float*)d_in[2];
    const float* w3  = (const float*)d_in[3];
    const float* w4  = (const float*)d_in[4];
    const float* w5  = (const float*)d_in[5];
    const float* w6  = (const float*)d_in[6];
    const float* w7  = (const float*)d_in[7];
    const float* w8  = (const float*)d_in[8];
    const float* w9  = (const float*)d_in[9];
    const float* g15 = (const float*)d_in[10];
    const float* b15 = (const float*)d_in[11];
    const float* m15 = (const float*)d_in[12];
    const float* v15 = (const float*)d_in[13];
    const float* g6  = (const float*)d_in[14];
    const float* b6  = (const float*)d_in[15];
    const float* m6  = (const float*)d_in[16];
    const float* v6  = (const float*)d_in[17];
    const float* g7  = (const float*)d_in[18];
    const float* b7  = (const float*)d_in[19];
    const float* m7  = (const float*)d_in[20];
    const float* v7  = (const float*)d_in[21];
    const float* g8  = (const float*)d_in[22];
    const float* b8  = (const float*)d_in[23];
    const float* m8  = (const float*)d_in[24];
    const float* v8  = (const float*)d_in[25];
    float* out = (float*)d_out;

    cudaFuncSetAttribute(edge2_kernel, cudaFuncAttributeMaxDynamicSharedMemorySize, 70656);
    cudaFuncSetAttribute(knn_kernel<3, 8>, cudaFuncAttributeMaxDynamicSharedMemorySize, 73728);
    cudaFuncSetAttribute(knn_kernel<64, 8>, cudaFuncAttributeMaxDynamicSharedMemorySize, 73728);

    dim3 eg(NPT / 4, B);
    dim3 kg(NPT / 8, B);
    int sqb = (B * NPT + 255) / 256;
    size_t ksm3  = 8 * 3 * 8  + 8 * NPT * 4;   // u64 queries + float s_neg
    size_t ksm64 = 8 * 64 * 8 + 8 * NPT * 4;

    // weight pre-conversion (independent of data path)
    convw_kernel<<<(1024 * 192 + 255) / 256, 256>>>(w6, 192, 0, 0, 1024, 192);
    convw_kernel<<<(512 * 192 + 255) / 256, 256>>>(w7, 1216, 1024, 196608, 512, 192);
    convw_kernel<<<(256 * 512 + 255) / 256, 256>>>(w8, 512, 0, 294912, 256, 512);
    glob_init_kernel<<<(B * 1024 + 255) / 256, 256>>>();

    // stage 1
    sq_kernel<3><<<sqb, 256>>>(x, 0);
    knn_kernel<3, 8><<<kg, 256, ksm3>>>(x, 0);
    edge1_kernel<<<eg, 256>>>(x, w1, w2, g15, b15, m15, v15);

    // stage 2
    sq_kernel<64><<<sqb, 256>>>(nullptr, 0);
    knn_kernel<64, 8><<<kg, 256, ksm64>>>(nullptr, 0);
    edge2_kernel<<<eg, 256, 70656>>>(w3, w4, g15, b15, m15, v15);

    // stage 3
    sq_kernel<64><<<sqb, 256>>>(nullptr, 64);
    knn_kernel<64, 8><<<kg, 256, ksm64>>>(nullptr, 64);
    edge3_kernel<<<eg, 256>>>(w5, g15, b15, m15, v15);

    // dense layers
    gemm_tc_kernel<<<dim3(B * NPT / TCBN, 8), 128>>>(0, 1024, 192, 0, 0, 0,
                                                     g6, b6, m6, v6);
    gemv7_kernel<<<(B * 512) / 8, 256>>>(w7);
    gemm_tc_kernel<<<dim3(B * NPT / TCBN, 4), 128>>>(196608, 512, 192, 0, 1, 1,
                                                     g7, b7, m7, v7);
    gemm_tc_kernel<<<dim3(B * NPT / TCBN, 2), 128>>>(294912, 256, 512, 2, 2, 0,
                                                     g8, b8, m8, v8);
    w9_kernel<<<B * NPT / 256, 256>>>(w9, out);
}